// round 4
// baseline (speedup 1.0000x reference)
#include <cuda_runtime.h>
#include <cuda_bf16.h>
#include <math.h>

#define NN 30000
#define EE 480000
#define DD 128
#define CAP 96          // padded CSR capacity (Poisson(16): P(deg>96) ~ 1e-40)
#define WPB 8           // warps (=nodes) per agg block; 30000/8 = 3750 exact

// ---------------- static device scratch (zero-initialized at module load) ----------------
__device__ float g_z[NN * DD];          // z = h @ W^T
__device__ float g_hout[NN * DD];       // aggregated output pre-BN
__device__ int   g_cursor[NN];          // per-node in-degree counter (self-cleaned by agg)
__device__ int   g_srcs[NN * CAP];      // padded CSR
__device__ float g_stats[2 * DD];       // sum / sumsq (self-cleaned by finalize)
__device__ float g_scale[DD];
__device__ float g_bias[DD];

__device__ __forceinline__ float ex2(float x) {
    float r; asm("ex2.approx.f32 %0, %1;" : "=f"(r) : "f"(x)); return r;
}

// ---------------- GEMM: 128x128 tile, 8x8 micro-tile, float4 smem ----------------
// z[n][o] = sum_k h[n][k] * W[o][k]
__global__ void __launch_bounds__(256) gemm_kernel(const float* __restrict__ h,
                                                   const float* __restrict__ W) {
    __shared__ float As[16][132];   // [kk][row], stride 132 kills STS bank conflicts
    __shared__ float Bs[16][132];   // [kk][col]
    int t = threadIdx.x;
    int tx = t & 15;                // col group: cols {4tx..4tx+3, 64+4tx..}
    int ty = t >> 4;                // row group: rows {4ty..4ty+3, 64+4ty..}
    int rowBase = blockIdx.x * 128;

    float acc[8][8];
#pragma unroll
    for (int i = 0; i < 8; i++)
#pragma unroll
        for (int j = 0; j < 8; j++) acc[i][j] = 0.f;

    for (int kc = 0; kc < DD; kc += 16) {
        // load A tile: 128 rows x 16 k  (512 float4, 2 per thread)
#pragma unroll
        for (int l = 0; l < 2; l++) {
            int idx = t + 256 * l;
            int row = idx >> 2, k4 = (idx & 3) * 4;
            int grow = rowBase + row;
            float4 v = (grow < NN) ? *(const float4*)&h[grow * DD + kc + k4]
                                   : make_float4(0.f, 0.f, 0.f, 0.f);
            As[k4 + 0][row] = v.x; As[k4 + 1][row] = v.y;
            As[k4 + 2][row] = v.z; As[k4 + 3][row] = v.w;
        }
        // load B tile: 128 cols x 16 k
#pragma unroll
        for (int l = 0; l < 2; l++) {
            int idx = t + 256 * l;
            int col = idx >> 2, k4 = (idx & 3) * 4;
            float4 v = *(const float4*)&W[col * DD + kc + k4];
            Bs[k4 + 0][col] = v.x; Bs[k4 + 1][col] = v.y;
            Bs[k4 + 2][col] = v.z; Bs[k4 + 3][col] = v.w;
        }
        __syncthreads();
#pragma unroll
        for (int kk = 0; kk < 16; kk++) {
            float4 a0 = *(const float4*)&As[kk][ty * 4];
            float4 a1 = *(const float4*)&As[kk][64 + ty * 4];
            float4 b0 = *(const float4*)&Bs[kk][tx * 4];
            float4 b1 = *(const float4*)&Bs[kk][64 + tx * 4];
            float a[8] = {a0.x, a0.y, a0.z, a0.w, a1.x, a1.y, a1.z, a1.w};
            float b[8] = {b0.x, b0.y, b0.z, b0.w, b1.x, b1.y, b1.z, b1.w};
#pragma unroll
            for (int i = 0; i < 8; i++)
#pragma unroll
                for (int j = 0; j < 8; j++) acc[i][j] = fmaf(a[i], b[j], acc[i][j]);
        }
        __syncthreads();
    }
#pragma unroll
    for (int i = 0; i < 8; i++) {
        int row = rowBase + ((i < 4) ? (ty * 4 + i) : (64 + ty * 4 + i - 4));
        if (row < NN) {
            *(float4*)&g_z[row * DD + tx * 4]      = *(float4*)&acc[i][0];
            *(float4*)&g_z[row * DD + 64 + tx * 4] = *(float4*)&acc[i][4];
        }
    }
}

// ---------------- build padded CSR ----------------
__global__ void build_kernel(const int* __restrict__ src, const int* __restrict__ dst) {
    int e = blockIdx.x * 256 + threadIdx.x;
    if (e < EE) {
        int d = dst[e];
        int pos = atomicAdd(&g_cursor[d], 1);
        if (pos < CAP) g_srcs[d * CAP + pos] = src[e];
    }
}

// ---------------- agg: warp-per-node, 4-edge MLP, fused BN stats ----------------
__global__ void __launch_bounds__(32 * WPB) agg_kernel(const float* __restrict__ snorm) {
    __shared__ int   ssrc[WPB][CAP];
    __shared__ float shv[WPB][DD];

    int w = threadIdx.x >> 5;
    int lane = threadIdx.x & 31;
    int d = blockIdx.x * WPB + w;

    int deg = g_cursor[d];
    if (deg > CAP) deg = CAP;
    if (lane == 0) g_cursor[d] = 0;          // self-clean for next replay

    for (int i = lane; i < deg; i += 32) ssrc[w][i] = g_srcs[d * CAP + i];

    const float L2E = 1.44269504f;
    float4 zd = *(const float4*)(g_z + d * DD + lane * 4);
    float4 ze;
    ze.x = zd.x * L2E; ze.y = zd.y * L2E; ze.z = zd.z * L2E; ze.w = zd.w * L2E;
    float sn = snorm[d];
    __syncwarp();

    float4 den0 = make_float4(0.f, 0.f, 0.f, 0.f), acc0 = den0;
    float4 den1 = den0, acc1 = den0;

#define PROC(V, DEN, ACC)                                                      \
    { float wt;                                                                \
      wt = ex2(V.x * ze.x); DEN.x += wt; ACC.x = fmaf(wt, V.x, ACC.x);         \
      wt = ex2(V.y * ze.y); DEN.y += wt; ACC.y = fmaf(wt, V.y, ACC.y);         \
      wt = ex2(V.z * ze.z); DEN.z += wt; ACC.z = fmaf(wt, V.z, ACC.z);         \
      wt = ex2(V.w * ze.w); DEN.w += wt; ACC.w = fmaf(wt, V.w, ACC.w); }

    int i = 0;
    for (; i + 4 <= deg; i += 4) {
        int s0 = ssrc[w][i], s1 = ssrc[w][i + 1], s2 = ssrc[w][i + 2], s3 = ssrc[w][i + 3];
        float4 va = *(const float4*)(g_z + s0 * DD + lane * 4);
        float4 vb = *(const float4*)(g_z + s1 * DD + lane * 4);
        float4 vc = *(const float4*)(g_z + s2 * DD + lane * 4);
        float4 vd = *(const float4*)(g_z + s3 * DD + lane * 4);
        PROC(va, den0, acc0);
        PROC(vb, den1, acc1);
        PROC(vc, den0, acc0);
        PROC(vd, den1, acc1);
    }
    for (; i < deg; i++) {
        int s0 = ssrc[w][i];
        float4 va = *(const float4*)(g_z + s0 * DD + lane * 4);
        PROC(va, den0, acc0);
    }
#undef PROC

    den0.x += den1.x; den0.y += den1.y; den0.z += den1.z; den0.w += den1.w;
    acc0.x += acc1.x; acc0.y += acc1.y; acc0.z += acc1.z; acc0.w += acc1.w;

    float4 hv;
    hv.x = (den0.x > 0.f) ? (acc0.x / den0.x) * sn : 0.f;
    hv.y = (den0.y > 0.f) ? (acc0.y / den0.y) * sn : 0.f;
    hv.z = (den0.z > 0.f) ? (acc0.z / den0.z) * sn : 0.f;
    hv.w = (den0.w > 0.f) ? (acc0.w / den0.w) * sn : 0.f;

    *(float4*)(g_hout + d * DD + lane * 4) = hv;
    *(float4*)(&shv[w][lane * 4]) = hv;
    __syncthreads();

    int tid = threadIdx.x;
    int c = tid & (DD - 1);
    if (tid < DD) {
        float s = 0.f;
#pragma unroll
        for (int ww = 0; ww < WPB; ww++) s += shv[ww][c];
        atomicAdd(&g_stats[c], s);
    } else {
        float s2 = 0.f;
#pragma unroll
        for (int ww = 0; ww < WPB; ww++) { float v = shv[ww][c]; s2 = fmaf(v, v, s2); }
        atomicAdd(&g_stats[DD + c], s2);
    }
}

// ---------------- fold BN stats into scale/bias, then self-clean ----------------
__global__ void finalize_kernel(const float* __restrict__ gamma,
                                const float* __restrict__ beta) {
    int c = threadIdx.x;
    const float invN = 1.f / (float)NN;
    float mu = g_stats[c] * invN;
    float var = g_stats[DD + c] * invN - mu * mu;
    float sc = rsqrtf(var + 1e-5f) * gamma[c];
    g_scale[c] = sc;
    g_bias[c] = beta[c] - mu * sc;
    g_stats[c] = 0.f;                 // self-clean for next replay
    g_stats[DD + c] = 0.f;
}

// ---------------- BN apply + ELU ----------------
__global__ void apply_kernel(float* __restrict__ out) {
    int q = blockIdx.x * 256 + threadIdx.x;
    if (q >= NN * DD / 4) return;
    int c4 = q & 31;
    float4 hv = *(const float4*)&g_hout[q * 4];
    float4 sc = *(const float4*)&g_scale[c4 * 4];
    float4 bi = *(const float4*)&g_bias[c4 * 4];
    float4 o;
    float v;
    v = fmaf(hv.x, sc.x, bi.x); o.x = (v > 0.f) ? v : expm1f(v);
    v = fmaf(hv.y, sc.y, bi.y); o.y = (v > 0.f) ? v : expm1f(v);
    v = fmaf(hv.z, sc.z, bi.z); o.z = (v > 0.f) ? v : expm1f(v);
    v = fmaf(hv.w, sc.w, bi.w); o.w = (v > 0.f) ? v : expm1f(v);
    *(float4*)&out[q * 4] = o;
}

// ---------------- launch ----------------
extern "C" void kernel_launch(void* const* d_in, const int* in_sizes, int n_in,
                              void* d_out, int out_size) {
    const float* h      = (const float*)d_in[0];
    const float* snorm  = (const float*)d_in[1];
    const float* W      = (const float*)d_in[2];
    const float* gamma  = (const float*)d_in[3];
    const float* beta   = (const float*)d_in[4];
    const int*   src    = (const int*)d_in[5];
    const int*   dst    = (const int*)d_in[6];
    float* out = (float*)d_out;

    build_kernel<<<(EE + 255) / 256, 256>>>(src, dst);
    gemm_kernel<<<(NN + 127) / 128, 256>>>(h, W);
    agg_kernel<<<NN / WPB, 32 * WPB>>>(snorm);
    finalize_kernel<<<1, DD>>>(gamma, beta);
    apply_kernel<<<(NN * DD / 4 + 255) / 256, 256>>>(out);
}